// round 5
// baseline (speedup 1.0000x reference)
#include <cuda_runtime.h>
#include <math.h>

#define B_SZ 2
#define S_SZ 2048
#define D_SZ 1024
#define H_SZ 16
#define DH   64
#define MROWS (B_SZ * S_SZ)   // 4096

// Scratch (device globals: allocation-free rule)
__device__ float g_Q[MROWS * D_SZ];
__device__ float g_K[MROWS * D_SZ];
__device__ float g_V[MROWS * D_SZ];
__device__ float g_A[MROWS * D_SZ];
__device__ float g_XR[MROWS * D_SZ];      // tf32-rounded x
__device__ float g_WQ[D_SZ * D_SZ];
__device__ float g_WK[D_SZ * D_SZ];
__device__ float g_WV[D_SZ * D_SZ];
__device__ float g_WO[D_SZ * D_SZ];

// ---------------------------------------------------------------------------
// helpers
// ---------------------------------------------------------------------------
__device__ __forceinline__ unsigned f2tf(float f) {
    unsigned u;
    asm("cvt.rna.tf32.f32 %0, %1;" : "=r"(u) : "f"(f));
    return u;
}
__device__ __forceinline__ float tfr(float f) { return __uint_as_float(f2tf(f)); }

__device__ __forceinline__ void mma_tf32(float d[4], const unsigned a[4],
                                         const unsigned b[2]) {
    asm("mma.sync.aligned.m16n8k8.row.col.f32.tf32.tf32.f32 "
        "{%0,%1,%2,%3},{%4,%5,%6,%7},{%8,%9},{%0,%1,%2,%3};"
        : "+f"(d[0]), "+f"(d[1]), "+f"(d[2]), "+f"(d[3])
        : "r"(a[0]), "r"(a[1]), "r"(a[2]), "r"(a[3]), "r"(b[0]), "r"(b[1]));
}

__device__ __forceinline__ void cp16(unsigned* smem_dst, const void* g) {
    unsigned sa = (unsigned)__cvta_generic_to_shared(smem_dst);
    asm volatile("cp.async.cg.shared.global [%0], [%1], 16;\n" :: "r"(sa), "l"(g));
}
#define CP_COMMIT() asm volatile("cp.async.commit_group;\n")
#define CP_WAIT(n)  asm volatile("cp.async.wait_group %0;\n" :: "n"(n))

// ---------------------------------------------------------------------------
// preround: x,W -> tf32-rounded copies (float4 grid-stride)
// ---------------------------------------------------------------------------
#define X_F4 (MROWS * D_SZ / 4)          // 1048576
#define W_F4 (D_SZ * D_SZ / 4)           // 262144
#define PR_TOTAL (X_F4 + 4 * W_F4)       // 2097152

__global__ __launch_bounds__(256) void preround_kernel(
    const float* __restrict__ x,
    const float* __restrict__ wq, const float* __restrict__ wk,
    const float* __restrict__ wv, const float* __restrict__ wo)
{
    int i = blockIdx.x * blockDim.x + threadIdx.x;
    if (i >= PR_TOTAL) return;
    const float4* src; float4* dst; int off;
    if (i < X_F4)               { src = (const float4*)x;  dst = (float4*)g_XR; off = i; }
    else if (i < X_F4 + W_F4)   { src = (const float4*)wq; dst = (float4*)g_WQ; off = i - X_F4; }
    else if (i < X_F4 + 2*W_F4) { src = (const float4*)wk; dst = (float4*)g_WK; off = i - X_F4 - W_F4; }
    else if (i < X_F4 + 3*W_F4) { src = (const float4*)wv; dst = (float4*)g_WV; off = i - X_F4 - 2*W_F4; }
    else                        { src = (const float4*)wo; dst = (float4*)g_WO; off = i - X_F4 - 3*W_F4; }
    float4 v = src[off];
    float4 r = { tfr(v.x), tfr(v.y), tfr(v.z), tfr(v.w) };
    dst[off] = r;
}

// ---------------------------------------------------------------------------
// tf32 GEMM, cp.async 2-stage pipeline, 2 CTAs/SM.
// BM=BN=128, BK=32, 256 threads (8 warps 2x4), warp tile 64x32.
// As stride 36 (==4 mod 32), Bs stride 136 (==8 mod 32): conflict-free frags.
// ---------------------------------------------------------------------------
#define GAPAD 36
#define GBPAD 136
#define AS_U32 (128 * GAPAD)                 // 4608
#define BS_U32 (32 * GBPAD)                  // 4352
#define STAGE_U32 (AS_U32 + BS_U32)          // 8960
#define GEMM_SMEM (2 * STAGE_U32 * 4)        // 71680 B

template<bool ROUND>
__device__ __forceinline__ void gemm_cp(
    const float* __restrict__ A, const float* __restrict__ W,
    const float* __restrict__ bias, float* __restrict__ C, int N, int K)
{
    extern __shared__ unsigned sm[];
    const int tid  = threadIdx.x;
    const int warp = tid >> 5, lane = tid & 31;
    const int lq = lane >> 2, lr = lane & 3;
    const int m0 = blockIdx.y * 128;
    const int n0 = blockIdx.x * 128;
    const int wm = (warp >> 2) * 64;
    const int wn = (warp & 3) * 32;

    float acc[4][4][4];
#pragma unroll
    for (int i = 0; i < 4; i++)
#pragma unroll
        for (int j = 0; j < 4; j++)
#pragma unroll
            for (int v = 0; v < 4; v++) acc[i][j][v] = 0.f;

    const int T = K / 32;

    auto issue = [&](int t) {
        unsigned* As = sm + (t & 1) * STAGE_U32;
        unsigned* Bs = As + AS_U32;
        const int k0 = t * 32;
#pragma unroll
        for (int i = 0; i < 4; i++) {
            int f = tid + i * 256;
            int row = f >> 3, c = (f & 7) * 4;
            cp16(&As[row * GAPAD + c], &A[(size_t)(m0 + row) * K + k0 + c]);
        }
#pragma unroll
        for (int i = 0; i < 4; i++) {
            int f = tid + i * 256;
            int kr = f >> 5, nc = (f & 31) * 4;
            cp16(&Bs[kr * GBPAD + nc], &W[(size_t)(k0 + kr) * N + n0 + nc]);
        }
    };

    issue(0); CP_COMMIT();

    for (int t = 0; t < T; t++) {
        if (t + 1 < T) {
            issue(t + 1); CP_COMMIT();
            CP_WAIT(1);              // stage t landed, stage t+1 in flight
        } else {
            CP_WAIT(0);
        }
        __syncthreads();

        const unsigned* As = sm + (t & 1) * STAGE_U32;
        const unsigned* Bs = As + AS_U32;
#pragma unroll
        for (int ks = 0; ks < 4; ks++) {
            const int k8 = ks * 8;
            unsigned a[4][4], b[4][2];
#pragma unroll
            for (int mt = 0; mt < 4; mt++) {
                int r = wm + mt * 16 + lq;
                a[mt][0] = As[r * GAPAD + k8 + lr];
                a[mt][1] = As[(r + 8) * GAPAD + k8 + lr];
                a[mt][2] = As[r * GAPAD + k8 + 4 + lr];
                a[mt][3] = As[(r + 8) * GAPAD + k8 + 4 + lr];
            }
#pragma unroll
            for (int nt = 0; nt < 4; nt++) {
                int c = wn + nt * 8 + lq;
                b[nt][0] = Bs[(k8 + lr) * GBPAD + c];
                b[nt][1] = Bs[(k8 + 4 + lr) * GBPAD + c];
            }
#pragma unroll
            for (int mt = 0; mt < 4; mt++)
#pragma unroll
                for (int nt = 0; nt < 4; nt++)
                    mma_tf32(acc[mt][nt], a[mt], b[nt]);
        }
        __syncthreads();             // readers done before stage t is rewritten
    }

    // Epilogue
#pragma unroll
    for (int mt = 0; mt < 4; mt++) {
#pragma unroll
        for (int nt = 0; nt < 4; nt++) {
            int r = m0 + wm + mt * 16 + lq;
            int c = n0 + wn + nt * 8 + 2 * lr;
            float b0 = bias[c], b1 = bias[c + 1];
            float2 v0, v1;
            if (ROUND) {
                v0 = { tfr(acc[mt][nt][0] + b0), tfr(acc[mt][nt][1] + b1) };
                v1 = { tfr(acc[mt][nt][2] + b0), tfr(acc[mt][nt][3] + b1) };
            } else {
                v0 = { acc[mt][nt][0] + b0, acc[mt][nt][1] + b1 };
                v1 = { acc[mt][nt][2] + b0, acc[mt][nt][3] + b1 };
            }
            *(float2*)&C[(size_t)r * N + c] = v0;
            *(float2*)&C[(size_t)(r + 8) * N + c] = v1;
        }
    }
}

__global__ __launch_bounds__(256, 2) void qkv_kernel(
    const float* __restrict__ bq, const float* __restrict__ bk,
    const float* __restrict__ bv)
{
    const float* W; const float* b; float* C;
    if (blockIdx.z == 0)      { W = g_WQ; b = bq; C = g_Q; }
    else if (blockIdx.z == 1) { W = g_WK; b = bk; C = g_K; }
    else                      { W = g_WV; b = bv; C = g_V; }
    gemm_cp<true>(g_XR, W, b, C, D_SZ, D_SZ);
}

__global__ __launch_bounds__(256, 2) void out_kernel(
    const float* __restrict__ bo, float* __restrict__ out)
{
    gemm_cp<false>(g_A, g_WO, bo, out, D_SZ, D_SZ);
}

// ---------------------------------------------------------------------------
// tf32 flash attention, cp.async double-buffered K/V, P kept in registers
// (accumulator -> A-fragment permute via width-4 shuffles).
// BQ=128, key tile 64, 8 warps x 16 q rows. 2 CTAs/SM.
// ---------------------------------------------------------------------------
#define AQ_STR 68   // Qs/Ks stride (==4 mod 32)
#define AV_STR 72   // Vs stride   (==8 mod 32)
#define A_QS 0
#define A_KS (128 * AQ_STR)                      // 8704
#define A_VS (A_KS + 2 * 64 * AQ_STR)            // 17408
#define ATTN_SMEM ((A_VS + 2 * 64 * AV_STR) * 4) // 106496 B

__global__ __launch_bounds__(256, 2) void attn_kernel(
    const float* __restrict__ Q, const float* __restrict__ K,
    const float* __restrict__ V, float* __restrict__ O)
{
    extern __shared__ unsigned sm[];
    unsigned* Qs = sm + A_QS;

    const int tid  = threadIdx.x;
    const int warp = tid >> 5, lane = tid & 31;
    const int lq = lane >> 2, lr = lane & 3;
    const int qt = gridDim.x - 1 - blockIdx.x;   // heavy tiles first
    const int h  = blockIdx.y;
    const int b  = blockIdx.z;
    const int q0 = qt * 128;
    const int wq = warp * 16;

    const float* Qg = Q + ((size_t)b * S_SZ + q0) * D_SZ + h * DH;

    // Stage Q (pre-scaled by 1/sqrt(dk)=0.125, re-rounded)
#pragma unroll
    for (int i = 0; i < 8; i++) {
        int f = tid + i * 256;
        int row = f >> 4, d = (f & 15) * 4;
        float4 v = *(const float4*)&Qg[(size_t)row * D_SZ + d];
        uint4 u = { f2tf(v.x * 0.125f), f2tf(v.y * 0.125f),
                    f2tf(v.z * 0.125f), f2tf(v.w * 0.125f) };
        *(uint4*)&Qs[row * AQ_STR + d] = u;
    }

    auto issue_kv = [&](int kt) {
        int st = kt & 1;
        unsigned* Ks = sm + A_KS + st * (64 * AQ_STR);
        unsigned* Vs = sm + A_VS + st * (64 * AV_STR);
        const float* Kg = K + ((size_t)b * S_SZ + kt * 64) * D_SZ + h * DH;
        const float* Vg = V + ((size_t)b * S_SZ + kt * 64) * D_SZ + h * DH;
#pragma unroll
        for (int i = 0; i < 4; i++) {
            int f = tid + i * 256;
            int row = f >> 4, d = (f & 15) * 4;
            cp16(&Ks[row * AQ_STR + d], &Kg[(size_t)row * D_SZ + d]);
            cp16(&Vs[row * AV_STR + d], &Vg[(size_t)row * D_SZ + d]);
        }
    };

    float o[8][4];
#pragma unroll
    for (int dt = 0; dt < 8; dt++)
#pragma unroll
        for (int v = 0; v < 4; v++) o[dt][v] = 0.f;
    float m0v = -INFINITY, m1v = -INFINITY;
    float l0v = 0.f, l1v = 0.f;

    const int nkt = 2 * qt + 2;
    issue_kv(0); CP_COMMIT();

    const int hsel = lr >> 1, esel = lr & 1;

    for (int kt = 0; kt < nkt; kt++) {
        CP_WAIT(0);
        __syncthreads();                 // stage kt data ready; prev readers done
        if (kt + 1 < nkt) issue_kv(kt + 1);
        CP_COMMIT();

        if (kt * 64 <= q0 + wq + 15) {   // warp has unmasked rows in this tile
            const unsigned* Ks = sm + A_KS + (kt & 1) * (64 * AQ_STR);
            const unsigned* Vs = sm + A_VS + (kt & 1) * (64 * AV_STR);

            // ---- S = Q K^T (16 x 64 per warp) ----
            float s[8][4];
#pragma unroll
            for (int nt = 0; nt < 8; nt++)
#pragma unroll
                for (int v = 0; v < 4; v++) s[nt][v] = 0.f;

#pragma unroll
            for (int ks = 0; ks < 8; ks++) {
                const int k8 = ks * 8;
                unsigned a[4];
                int r = wq + lq;
                a[0] = Qs[r * AQ_STR + k8 + lr];
                a[1] = Qs[(r + 8) * AQ_STR + k8 + lr];
                a[2] = Qs[r * AQ_STR + k8 + 4 + lr];
                a[3] = Qs[(r + 8) * AQ_STR + k8 + 4 + lr];
#pragma unroll
                for (int nt = 0; nt < 8; nt++) {
                    unsigned bf[2];
                    int c = nt * 8 + lq;
                    bf[0] = Ks[c * AQ_STR + k8 + lr];
                    bf[1] = Ks[c * AQ_STR + k8 + 4 + lr];
                    mma_tf32(s[nt], a, bf);
                }
            }

            // ---- causal mask ----
            if (kt >= 2 * qt) {
                int qr0 = q0 + wq + lq, qr1 = qr0 + 8;
#pragma unroll
                for (int nt = 0; nt < 8; nt++) {
                    int kb = kt * 64 + nt * 8 + 2 * lr;
                    if (kb > qr0)     s[nt][0] = -INFINITY;
                    if (kb + 1 > qr0) s[nt][1] = -INFINITY;
                    if (kb > qr1)     s[nt][2] = -INFINITY;
                    if (kb + 1 > qr1) s[nt][3] = -INFINITY;
                }
            }

            // ---- online softmax ----
            float mx0 = s[0][0], mx1 = s[0][2];
#pragma unroll
            for (int nt = 0; nt < 8; nt++) {
                mx0 = fmaxf(mx0, fmaxf(s[nt][0], s[nt][1]));
                mx1 = fmaxf(mx1, fmaxf(s[nt][2], s[nt][3]));
            }
            mx0 = fmaxf(mx0, __shfl_xor_sync(0xffffffff, mx0, 1));
            mx0 = fmaxf(mx0, __shfl_xor_sync(0xffffffff, mx0, 2));
            mx1 = fmaxf(mx1, __shfl_xor_sync(0xffffffff, mx1, 1));
            mx1 = fmaxf(mx1, __shfl_xor_sync(0xffffffff, mx1, 2));

            float mn0 = fmaxf(m0v, mx0), mn1 = fmaxf(m1v, mx1);
            float al0 = __expf(m0v - mn0), al1 = __expf(m1v - mn1);
            m0v = mn0; m1v = mn1;

            float ls0 = 0.f, ls1 = 0.f;
#pragma unroll
            for (int nt = 0; nt < 8; nt++) {
                float p0 = __expf(s[nt][0] - mn0);
                float p1 = __expf(s[nt][1] - mn0);
                float p2 = __expf(s[nt][2] - mn1);
                float p3 = __expf(s[nt][3] - mn1);
                ls0 += p0 + p1; ls1 += p2 + p3;
                s[nt][0] = __uint_as_float(f2tf(p0));
                s[nt][1] = __uint_as_float(f2tf(p1));
                s[nt][2] = __uint_as_float(f2tf(p2));
                s[nt][3] = __uint_as_float(f2tf(p3));
            }
            ls0 += __shfl_xor_sync(0xffffffff, ls0, 1);
            ls0 += __shfl_xor_sync(0xffffffff, ls0, 2);
            ls1 += __shfl_xor_sync(0xffffffff, ls1, 1);
            ls1 += __shfl_xor_sync(0xffffffff, ls1, 2);
            l0v = l0v * al0 + ls0;
            l1v = l1v * al1 + ls1;

#pragma unroll
            for (int dt = 0; dt < 8; dt++) {
                o[dt][0] *= al0; o[dt][1] *= al0;
                o[dt][2] *= al1; o[dt][3] *= al1;
            }

            // ---- O += P V : A-frag from accumulator via width-4 shuffles ----
#pragma unroll
            for (int ks = 0; ks < 8; ks++) {
                float x0 = __shfl_sync(0xffffffff, s[ks][0], hsel, 4);
                float x1 = __shfl_sync(0xffffffff, s[ks][1], hsel, 4);
                float x2 = __shfl_sync(0xffffffff, s[ks][2], hsel, 4);
                float x3 = __shfl_sync(0xffffffff, s[ks][3], hsel, 4);
                float y0 = __shfl_sync(0xffffffff, s[ks][0], hsel + 2, 4);
                float y1 = __shfl_sync(0xffffffff, s[ks][1], hsel + 2, 4);
                float y2 = __shfl_sync(0xffffffff, s[ks][2], hsel + 2, 4);
                float y3 = __shfl_sync(0xffffffff, s[ks][3], hsel + 2, 4);
                unsigned a[4];
                a[0] = __float_as_uint(esel ? x1 : x0);
                a[1] = __float_as_uint(esel ? x3 : x2);
                a[2] = __float_as_uint(esel ? y1 : y0);
                a[3] = __float_as_uint(esel ? y3 : y2);
                const int k8 = ks * 8;
#pragma unroll
                for (int dt = 0; dt < 8; dt++) {
                    unsigned bf[2];
                    int c = dt * 8 + lq;
                    bf[0] = Vs[(k8 + lr) * AV_STR + c];
                    bf[1] = Vs[(k8 + 4 + lr) * AV_STR + c];
                    mma_tf32(o[dt], a, bf);
                }
            }
        }
    }

    // ---- epilogue: normalize + store (rounded: feeds out-proj cp.async) ----
    float inv0 = 1.f / l0v, inv1 = 1.f / l1v;
    int gr0 = q0 + wq + lq;
#pragma unroll
    for (int dt = 0; dt < 8; dt++) {
        int col = dt * 8 + 2 * lr;
        float2 v0 = { tfr(o[dt][0] * inv0), tfr(o[dt][1] * inv0) };
        float2 v1 = { tfr(o[dt][2] * inv1), tfr(o[dt][3] * inv1) };
        *(float2*)&O[((size_t)b * S_SZ + gr0) * D_SZ + h * DH + col] = v0;
        *(float2*)&O[((size_t)b * S_SZ + gr0 + 8) * D_SZ + h * DH + col] = v1;
    }
}

// ---------------------------------------------------------------------------

extern "C" void kernel_launch(void* const* d_in, const int* in_sizes, int n_in,
                              void* d_out, int out_size)
{
    const float* x  = (const float*)d_in[0];
    const float* Wq = (const float*)d_in[1];
    const float* bq = (const float*)d_in[2];
    const float* Wk = (const float*)d_in[3];
    const float* bk = (const float*)d_in[4];
    const float* Wv = (const float*)d_in[5];
    const float* bv = (const float*)d_in[6];
    const float* Wo = (const float*)d_in[7];
    const float* bo = (const float*)d_in[8];
    float* out = (float*)d_out;

    cudaFuncSetAttribute(qkv_kernel,
                         cudaFuncAttributeMaxDynamicSharedMemorySize, GEMM_SMEM);
    cudaFuncSetAttribute(out_kernel,
                         cudaFuncAttributeMaxDynamicSharedMemorySize, GEMM_SMEM);
    cudaFuncSetAttribute(attn_kernel,
                         cudaFuncAttributeMaxDynamicSharedMemorySize, ATTN_SMEM);

    float* gq; cudaGetSymbolAddress((void**)&gq, g_Q);
    float* gk; cudaGetSymbolAddress((void**)&gk, g_K);
    float* gv; cudaGetSymbolAddress((void**)&gv, g_V);
    float* ga; cudaGetSymbolAddress((void**)&ga, g_A);

    // 0) tf32 pre-round of x and weights
    preround_kernel<<<(PR_TOTAL + 255) / 256, 256>>>(x, Wq, Wk, Wv, Wo);

    // 1) fused QKV projections (rounded epilogue)
    dim3 g1(D_SZ / 128, MROWS / 128, 3);
    qkv_kernel<<<g1, 256, GEMM_SMEM>>>(bq, bk, bv);

    // 2) causal flash attention -> g_A (rounded epilogue)
    dim3 g2(S_SZ / 128, H_SZ, B_SZ);
    attn_kernel<<<g2, 256, ATTN_SMEM>>>(gq, gk, gv, ga);

    // 3) output projection (fp32 epilogue)
    dim3 g3(D_SZ / 128, MROWS / 128);
    out_kernel<<<g3, 256, GEMM_SMEM>>>(bo, out);
}

// round 8
// speedup vs baseline: 1.9844x; 1.9844x over previous
#include <cuda_runtime.h>
#include <cuda_fp16.h>
#include <math.h>
#include <cstdint>

#define B_SZ 2
#define S_SZ 2048
#define D_SZ 1024
#define H_SZ 16
#define DH   64
#define MROWS (B_SZ * S_SZ)   // 4096

// Scratch (device globals: allocation-free rule)
__device__ __half g_Q[MROWS * D_SZ];
__device__ __half g_K[MROWS * D_SZ];
__device__ __half g_V[MROWS * D_SZ];
__device__ __half g_A[MROWS * D_SZ];
__device__ __half g_XR[MROWS * D_SZ];     // fp16 x
__device__ __half g_WQ[D_SZ * D_SZ];      // fp16 transposed weights [N][K]
__device__ __half g_WK[D_SZ * D_SZ];
__device__ __half g_WV[D_SZ * D_SZ];
__device__ __half g_WO[D_SZ * D_SZ];

// ---------------------------------------------------------------------------
// helpers
// ---------------------------------------------------------------------------
__device__ __forceinline__ void mma_f16(float d[4], const unsigned a[4],
                                        const unsigned b[2]) {
    asm("mma.sync.aligned.m16n8k16.row.col.f32.f16.f16.f32 "
        "{%0,%1,%2,%3},{%4,%5,%6,%7},{%8,%9},{%0,%1,%2,%3};"
        : "+f"(d[0]), "+f"(d[1]), "+f"(d[2]), "+f"(d[3])
        : "r"(a[0]), "r"(a[1]), "r"(a[2]), "r"(a[3]), "r"(b[0]), "r"(b[1]));
}

__device__ __forceinline__ void ldsm_x4(unsigned r[4], unsigned addr) {
    asm volatile("ldmatrix.sync.aligned.m8n8.x4.shared.b16 {%0,%1,%2,%3}, [%4];"
        : "=r"(r[0]), "=r"(r[1]), "=r"(r[2]), "=r"(r[3]) : "r"(addr));
}
__device__ __forceinline__ void ldsm_x2(unsigned r[2], unsigned addr) {
    asm volatile("ldmatrix.sync.aligned.m8n8.x2.shared.b16 {%0,%1}, [%2];"
        : "=r"(r[0]), "=r"(r[1]) : "r"(addr));
}
__device__ __forceinline__ void ldsm_x2t(unsigned r[2], unsigned addr) {
    asm volatile("ldmatrix.sync.aligned.m8n8.x2.trans.shared.b16 {%0,%1}, [%2];"
        : "=r"(r[0]), "=r"(r[1]) : "r"(addr));
}

__device__ __forceinline__ void cp16(void* smem_dst, const void* g) {
    unsigned sa = (unsigned)__cvta_generic_to_shared(smem_dst);
    asm volatile("cp.async.cg.shared.global [%0], [%1], 16;\n" :: "r"(sa), "l"(g));
}
#define CP_COMMIT() asm volatile("cp.async.commit_group;\n")
#define CP_WAIT(n)  asm volatile("cp.async.wait_group %0;\n" :: "n"(n))

__device__ __forceinline__ unsigned h2u(__half2 h) {
    return *reinterpret_cast<unsigned*>(&h);
}

// ---------------------------------------------------------------------------
// preround: x -> fp16 (float4 -> 2x half2)
// ---------------------------------------------------------------------------
#define X_F4 (MROWS * D_SZ / 4)          // 1048576

__global__ __launch_bounds__(256) void preround_x_kernel(const float* __restrict__ x)
{
    int i = blockIdx.x * blockDim.x + threadIdx.x;
    if (i >= X_F4) return;
    float4 v = ((const float4*)x)[i];
    __half2 h0 = __floats2half2_rn(v.x, v.y);
    __half2 h1 = __floats2half2_rn(v.z, v.w);
    uint2 u = { h2u(h0), h2u(h1) };
    ((uint2*)g_XR)[i] = u;
}

// Weights: transpose [K][N] -> [N][K] with fp16 convert
__global__ __launch_bounds__(256) void wtrans_kernel(
    const float* __restrict__ wq, const float* __restrict__ wk,
    const float* __restrict__ wv, const float* __restrict__ wo)
{
    __shared__ float ts[32][33];
    const float* src; __half* dst;
    if (blockIdx.z == 0)      { src = wq; dst = g_WQ; }
    else if (blockIdx.z == 1) { src = wk; dst = g_WK; }
    else if (blockIdx.z == 2) { src = wv; dst = g_WV; }
    else                      { src = wo; dst = g_WO; }
    int nb = blockIdx.x * 32, kb = blockIdx.y * 32;
    int tx = threadIdx.x & 31, ty = threadIdx.x >> 5;
#pragma unroll
    for (int i = 0; i < 4; i++) {
        int k = kb + ty + i * 8;
        ts[ty + i * 8][tx] = src[(size_t)k * D_SZ + nb + tx];
    }
    __syncthreads();
#pragma unroll
    for (int i = 0; i < 4; i++) {
        int n = nb + ty + i * 8;
        dst[(size_t)n * D_SZ + kb + tx] = __float2half_rn(ts[tx][ty + i * 8]);
    }
}

// ---------------------------------------------------------------------------
// fp16 GEMM: C[M,N] = A[M,K] @ Wt^T + bias   (Wt is [N][K] fp16)
// BM=BN=128, BK=64, 256 threads (8 warps 2x4), warp tile 64x32.
// smem rows stride 72 halves (144B): ldmatrix rows hit distinct 16B banks,
// 2-stage cp.async, 2 CTAs/SM.
// ---------------------------------------------------------------------------
#define SH 72
#define TILE_B (128 * SH * 2)            // 18432 B per operand tile
#define STAGE_B (2 * TILE_B)             // 36864
#define GEMM_SMEM (2 * STAGE_B)          // 73728

template<bool HALF_OUT>
__device__ __forceinline__ void gemm_h(
    const __half* __restrict__ A, const __half* __restrict__ Wt,
    const float* __restrict__ bias, void* Cv, float scale, int N, int K)
{
    extern __shared__ char smc[];
    const unsigned sbase = (unsigned)__cvta_generic_to_shared(smc);
    const int tid  = threadIdx.x;
    const int warp = tid >> 5, lane = tid & 31;
    const int lq = lane >> 2, lr = lane & 3;
    const int m0 = blockIdx.y * 128;
    const int n0 = blockIdx.x * 128;
    const int wm = (warp >> 2) * 64;
    const int wn = (warp & 3) * 32;

    float acc[4][4][4];
#pragma unroll
    for (int i = 0; i < 4; i++)
#pragma unroll
        for (int j = 0; j < 4; j++)
#pragma unroll
            for (int v = 0; v < 4; v++) acc[i][j][v] = 0.f;

    const int T = K / 64;

    auto issue = [&](int t) {
        char* As = smc + (t & 1) * STAGE_B;
        char* Bs = As + TILE_B;
        const int k0 = t * 64;
#pragma unroll
        for (int i = 0; i < 4; i++) {
            int g = tid + i * 256;
            int row = g >> 3, j = g & 7;       // 128 rows x 8 chunks(16B)
            cp16(As + row * (SH * 2) + j * 16,
                 &A[(size_t)(m0 + row) * K + k0 + j * 8]);
        }
#pragma unroll
        for (int i = 0; i < 4; i++) {
            int g = tid + i * 256;
            int row = g >> 3, j = g & 7;
            cp16(Bs + row * (SH * 2) + j * 16,
                 &Wt[(size_t)(n0 + row) * K + k0 + j * 8]);
        }
    };

    issue(0); CP_COMMIT();

    // ldmatrix lane addressing (within-tile offsets)
    const int a_r = ((lane >> 3) & 1) * 8 + (lane & 7);  // m sub-row
    const int a_k = (lane >> 4) * 8;                      // k sub-col
    const int la  = lane & 15;
    const int b_r = la & 7;                               // n sub-row
    const int b_k = ((la >> 3) & 1) * 8;                  // k sub-col

    for (int t = 0; t < T; t++) {
        if (t + 1 < T) { issue(t + 1); CP_COMMIT(); CP_WAIT(1); }
        else           { CP_WAIT(0); }
        __syncthreads();

        const unsigned As = sbase + (t & 1) * STAGE_B;
        const unsigned Bs = As + TILE_B;
#pragma unroll
        for (int ks = 0; ks < 4; ks++) {
            const int k16 = ks * 16;
            unsigned a[4][4], b[4][2];
#pragma unroll
            for (int mt = 0; mt < 4; mt++)
                ldsm_x4(a[mt], As + ((wm + mt * 16 + a_r) * SH + k16 + a_k) * 2);
#pragma unroll
            for (int nt = 0; nt < 4; nt++)
                ldsm_x2(b[nt], Bs + ((wn + nt * 8 + b_r) * SH + k16 + b_k) * 2);
#pragma unroll
            for (int mt = 0; mt < 4; mt++)
#pragma unroll
                for (int nt = 0; nt < 4; nt++)
                    mma_f16(acc[mt][nt], a[mt], b[nt]);
        }
        __syncthreads();
    }

    // Epilogue: (acc + bias) * scale
#pragma unroll
    for (int mt = 0; mt < 4; mt++) {
#pragma unroll
        for (int nt = 0; nt < 4; nt++) {
            int r = m0 + wm + mt * 16 + lq;
            int c = n0 + wn + nt * 8 + 2 * lr;
            float b0 = bias[c], b1 = bias[c + 1];
            float v00 = (acc[mt][nt][0] + b0) * scale;
            float v01 = (acc[mt][nt][1] + b1) * scale;
            float v10 = (acc[mt][nt][2] + b0) * scale;
            float v11 = (acc[mt][nt][3] + b1) * scale;
            if (HALF_OUT) {
                __half* C = (__half*)Cv;
                *(__half2*)&C[(size_t)r * N + c]       = __floats2half2_rn(v00, v01);
                *(__half2*)&C[(size_t)(r + 8) * N + c] = __floats2half2_rn(v10, v11);
            } else {
                float* C = (float*)Cv;
                float2 f0 = { v00, v01 }, f1 = { v10, v11 };
                *(float2*)&C[(size_t)r * N + c] = f0;
                *(float2*)&C[(size_t)(r + 8) * N + c] = f1;
            }
        }
    }
}

__global__ __launch_bounds__(256, 2) void qkv_kernel(
    const float* __restrict__ bq, const float* __restrict__ bk,
    const float* __restrict__ bv)
{
    const __half* W; const float* b; __half* C; float scl;
    if (blockIdx.z == 0)      { W = g_WQ; b = bq; C = g_Q; scl = 0.125f; }
    else if (blockIdx.z == 1) { W = g_WK; b = bk; C = g_K; scl = 1.0f; }
    else                      { W = g_WV; b = bv; C = g_V; scl = 1.0f; }
    gemm_h<true>(g_XR, W, b, C, scl, D_SZ, D_SZ);
}

__global__ __launch_bounds__(256, 2) void out_kernel(
    const float* __restrict__ bo, float* __restrict__ out)
{
    gemm_h<false>(g_A, g_WO, bo, out, 1.0f, D_SZ, D_SZ);
}

// ---------------------------------------------------------------------------
// fp16 flash attention. BQ=128, key tile 64, 8 warps x 16 q rows.
// Q pre-scaled by 1/8 in qkv epilogue -> raw cp.async staging.
// QK^T: Q A-frag via ldmatrix.x4, K B-frag via ldmatrix.x2 (K stored [kv][d]).
// PV: P stays in accumulator registers (fp16 acc layout == A-frag layout),
//     V B-frag via ldmatrix.x2.trans (V stored [kv][d]).
// ---------------------------------------------------------------------------
#define A_QS_B 0
#define A_KS_B (128 * SH * 2)                     // 18432
#define A_VS_B (A_KS_B + 2 * 64 * SH * 2)         // 36864
#define ATTN_SMEM (A_VS_B + 2 * 64 * SH * 2)      // 55296

__global__ __launch_bounds__(256, 2) void attn_kernel(
    const __half* __restrict__ Q, const __half* __restrict__ K,
    const __half* __restrict__ V, __half* __restrict__ O)
{
    extern __shared__ char smc[];
    const unsigned sbase = (unsigned)__cvta_generic_to_shared(smc);

    const int tid  = threadIdx.x;
    const int warp = tid >> 5, lane = tid & 31;
    const int lq = lane >> 2, lr = lane & 3;
    const int qt = gridDim.x - 1 - blockIdx.x;   // heavy tiles first
    const int h  = blockIdx.y;
    const int b  = blockIdx.z;
    const int q0 = qt * 128;
    const int wq = warp * 16;

    // Stage Q (half, pre-scaled): 128 rows x 64 halves
    const __half* Qg = Q + ((size_t)b * S_SZ + q0) * D_SZ + h * DH;
#pragma unroll
    for (int i = 0; i < 4; i++) {
        int g = tid + i * 256;
        int row = g >> 3, j = g & 7;
        cp16(smc + A_QS_B + row * (SH * 2) + j * 16,
             &Qg[(size_t)row * D_SZ + j * 8]);
    }

    auto issue_kv = [&](int kt) {
        int st = kt & 1;
        char* Ks = smc + A_KS_B + st * (64 * SH * 2);
        char* Vs = smc + A_VS_B + st * (64 * SH * 2);
        const __half* Kg = K + ((size_t)b * S_SZ + kt * 64) * D_SZ + h * DH;
        const __half* Vg = V + ((size_t)b * S_SZ + kt * 64) * D_SZ + h * DH;
#pragma unroll
        for (int i = 0; i < 2; i++) {
            int g = tid + i * 256;
            int row = g >> 3, j = g & 7;
            cp16(Ks + row * (SH * 2) + j * 16, &Kg[(size_t)row * D_SZ + j * 8]);
            cp16(Vs + row * (SH * 2) + j * 16, &Vg[(size_t)row * D_SZ + j * 8]);
        }
    };

    float o[8][4];
#pragma unroll
    for (int dt = 0; dt < 8; dt++)
#pragma unroll
        for (int v = 0; v < 4; v++) o[dt][v] = 0.f;
    float m0v = -INFINITY, m1v = -INFINITY;
    float l0v = 0.f, l1v = 0.f;

    const int nkt = 2 * qt + 2;
    issue_kv(0); CP_COMMIT();

    // ldmatrix lane addressing
    const int a_r = ((lane >> 3) & 1) * 8 + (lane & 7);
    const int a_k = (lane >> 4) * 8;
    const int la  = lane & 15;
    const int b_r = la & 7;
    const int b_k = ((la >> 3) & 1) * 8;

    for (int kt = 0; kt < nkt; kt++) {
        CP_WAIT(0);
        __syncthreads();                 // stage kt ready; prev readers done
        if (kt + 1 < nkt) issue_kv(kt + 1);
        CP_COMMIT();

        if (kt * 64 <= q0 + wq + 15) {
            const unsigned Ks = sbase + A_KS_B + (kt & 1) * (64 * SH * 2);
            const unsigned Vs = sbase + A_VS_B + (kt & 1) * (64 * SH * 2);
            const unsigned Qs = sbase + A_QS_B;

            // ---- S = Q K^T (16 x 64 per warp) ----
            float s[8][4];
#pragma unroll
            for (int nt = 0; nt < 8; nt++)
#pragma unroll
                for (int v = 0; v < 4; v++) s[nt][v] = 0.f;

#pragma unroll
            for (int ks = 0; ks < 4; ks++) {
                const int k16 = ks * 16;
                unsigned a[4];
                ldsm_x4(a, Qs + ((wq + a_r) * SH + k16 + a_k) * 2);
#pragma unroll
                for (int nt = 0; nt < 8; nt++) {
                    unsigned bf[2];
                    ldsm_x2(bf, Ks + ((nt * 8 + b_r) * SH + k16 + b_k) * 2);
                    mma_f16(s[nt], a, bf);
                }
            }

            // ---- causal mask (near-diagonal tiles only) ----
            if (kt >= 2 * qt) {
                int qr0 = q0 + wq + lq, qr1 = qr0 + 8;
#pragma unroll
                for (int nt = 0; nt < 8; nt++) {
                    int kb = kt * 64 + nt * 8 + 2 * lr;
                    if (kb > qr0)     s[nt][0] = -INFINITY;
                    if (kb + 1 > qr0) s[nt][1] = -INFINITY;
                    if (kb > qr1)     s[nt][2] = -INFINITY;
                    if (kb + 1 > qr1) s[nt][3] = -INFINITY;
                }
            }

            // ---- online softmax ----
            float mx0 = s[0][0], mx1 = s[0][2];
#pragma unroll
            for (int nt = 0; nt < 8; nt++) {
                mx0 = fmaxf(mx0, fmaxf(s[nt][0], s[nt][1]));
                mx1 = fmaxf(mx1, fmaxf(s[nt][2], s[nt][3]));
            }
            mx0 = fmaxf(mx0, __shfl_xor_sync(0xffffffff, mx0, 1));
            mx0 = fmaxf(mx0, __shfl_xor_sync(0xffffffff, mx0, 2));
            mx1 = fmaxf(mx1, __shfl_xor_sync(0xffffffff, mx1, 1));
            mx1 = fmaxf(mx1, __shfl_xor_sync(0xffffffff, mx1, 2));

            float mn0 = fmaxf(m0v, mx0), mn1 = fmaxf(m1v, mx1);
            float al0 = __expf(m0v - mn0), al1 = __expf(m1v - mn1);
            m0v = mn0; m1v = mn1;

            float ls0 = 0.f, ls1 = 0.f;
            unsigned ph[8][2];       // packed P: [nt][0]=rows lq (c0,c1), [1]=rows lq+8
#pragma unroll
            for (int nt = 0; nt < 8; nt++) {
                float p0 = __expf(s[nt][0] - mn0);
                float p1 = __expf(s[nt][1] - mn0);
                float p2 = __expf(s[nt][2] - mn1);
                float p3 = __expf(s[nt][3] - mn1);
                ls0 += p0 + p1; ls1 += p2 + p3;
                ph[nt][0] = h2u(__floats2half2_rn(p0, p1));
                ph[nt][1] = h2u(__floats2half2_rn(p2, p3));
            }
            ls0 += __shfl_xor_sync(0xffffffff, ls0, 1);
            ls0 += __shfl_xor_sync(0xffffffff, ls0, 2);
            ls1 += __shfl_xor_sync(0xffffffff, ls1, 1);
            ls1 += __shfl_xor_sync(0xffffffff, ls1, 2);
            l0v = l0v * al0 + ls0;
            l1v = l1v * al1 + ls1;

#pragma unroll
            for (int dt = 0; dt < 8; dt++) {
                o[dt][0] *= al0; o[dt][1] *= al0;
                o[dt][2] *= al1; o[dt][3] *= al1;
            }

            // ---- O += P V ----
            // A-frag for k16 chunk ks: {ph[2ks][0], ph[2ks][1], ph[2ks+1][0], ph[2ks+1][1]}
#pragma unroll
            for (int ks = 0; ks < 4; ks++) {
                unsigned a[4] = { ph[2 * ks][0], ph[2 * ks][1],
                                  ph[2 * ks + 1][0], ph[2 * ks + 1][1] };
#pragma unroll
                for (int dt = 0; dt < 8; dt++) {
                    unsigned bf[2];
                    ldsm_x2t(bf, Vs + ((ks * 16 + la) * SH + dt * 8) * 2);
                    mma_f16(o[dt], a, bf);
                }
            }
        }
    }

    // ---- epilogue: normalize + fp16 store ----
    float inv0 = 1.f / l0v, inv1 = 1.f / l1v;
    int gr0 = q0 + wq + lq;
#pragma unroll
    for (int dt = 0; dt < 8; dt++) {
        int col = dt * 8 + 2 * lr;
        __half2 v0 = __floats2half2_rn(o[dt][0] * inv0, o[dt][1] * inv0);
        __half2 v1 = __floats2half2_rn(o[dt][2] * inv1, o[dt][3] * inv1);
        *(__half2*)&O[((size_t)b * S_SZ + gr0) * D_SZ + h * DH + col] = v0;
        *(__half2*)&O[((size_t)b * S_SZ + gr0 + 8) * D_SZ + h * DH + col] = v1;
    }
}

// ---------------------------------------------------------------------------

extern "C" void kernel_launch(void* const* d_in, const int* in_sizes, int n_in,
                              void* d_out, int out_size)
{
    const float* x  = (const float*)d_in[0];
    const float* Wq = (const float*)d_in[1];
    const float* bq = (const float*)d_in[2];
    const float* Wk = (const float*)d_in[3];
    const float* bk = (const float*)d_in[4];
    const float* Wv = (const float*)d_in[5];
    const float* bv = (const float*)d_in[6];
    const float* Wo = (const float*)d_in[7];
    const float* bo = (const float*)d_in[8];
    float* out = (float*)d_out;

    cudaFuncSetAttribute(qkv_kernel,
                         cudaFuncAttributeMaxDynamicSharedMemorySize, GEMM_SMEM);
    cudaFuncSetAttribute(out_kernel,
                         cudaFuncAttributeMaxDynamicSharedMemorySize, GEMM_SMEM);
    cudaFuncSetAttribute(attn_kernel,
                         cudaFuncAttributeMaxDynamicSharedMemorySize, ATTN_SMEM);

    __half* gq; cudaGetSymbolAddress((void**)&gq, g_Q);
    __half* gk; cudaGetSymbolAddress((void**)&gk, g_K);
    __half* gv; cudaGetSymbolAddress((void**)&gv, g_V);
    __half* ga; cudaGetSymbolAddress((void**)&ga, g_A);

    // 0) fp16 convert x; transpose+convert weights to [N][K]
    preround_x_kernel<<<(X_F4 + 255) / 256, 256>>>(x);
    wtrans_kernel<<<dim3(32, 32, 4), 256>>>(Wq, Wk, Wv, Wo);

    // 1) QKV projections (fp16 mma; Q epilogue folds 1/sqrt(dk))
    dim3 g1(D_SZ / 128, MROWS / 128, 3);
    qkv_kernel<<<g1, 256, GEMM_SMEM>>>(bq, bk, bv);

    // 2) causal flash attention -> g_A (fp16)
    dim3 g2(S_SZ / 128, H_SZ, B_SZ);
    attn_kernel<<<g2, 256, ATTN_SMEM>>>(gq, gk, gv, ga);

    // 3) output projection (fp32 out)
    dim3 g3(D_SZ / 128, MROWS / 128);
    out_kernel<<<g3, 256, GEMM_SMEM>>>(bo, out);
}

// round 9
// speedup vs baseline: 2.0022x; 1.0090x over previous
#include <cuda_runtime.h>
#include <cuda_fp16.h>
#include <math.h>
#include <cstdint>

#define B_SZ 2
#define S_SZ 2048
#define D_SZ 1024
#define H_SZ 16
#define DH   64
#define MROWS (B_SZ * S_SZ)   // 4096

// Scratch (device globals: allocation-free rule)
__device__ __half g_Q[MROWS * D_SZ];
__device__ __half g_K[MROWS * D_SZ];
__device__ __half g_V[MROWS * D_SZ];
__device__ __half g_A[MROWS * D_SZ];
__device__ __half g_XR[MROWS * D_SZ];     // fp16 x
__device__ __half g_WQ[D_SZ * D_SZ];      // fp16 transposed weights [N][K]
__device__ __half g_WK[D_SZ * D_SZ];
__device__ __half g_WV[D_SZ * D_SZ];
__device__ __half g_WO[D_SZ * D_SZ];

// ---------------------------------------------------------------------------
// helpers
// ---------------------------------------------------------------------------
__device__ __forceinline__ void mma_f16(float d[4], const unsigned a[4],
                                        const unsigned b[2]) {
    asm("mma.sync.aligned.m16n8k16.row.col.f32.f16.f16.f32 "
        "{%0,%1,%2,%3},{%4,%5,%6,%7},{%8,%9},{%0,%1,%2,%3};"
        : "+f"(d[0]), "+f"(d[1]), "+f"(d[2]), "+f"(d[3])
        : "r"(a[0]), "r"(a[1]), "r"(a[2]), "r"(a[3]), "r"(b[0]), "r"(b[1]));
}

__device__ __forceinline__ void ldsm_x4(unsigned r[4], unsigned addr) {
    asm volatile("ldmatrix.sync.aligned.m8n8.x4.shared.b16 {%0,%1,%2,%3}, [%4];"
        : "=r"(r[0]), "=r"(r[1]), "=r"(r[2]), "=r"(r[3]) : "r"(addr));
}
__device__ __forceinline__ void ldsm_x2(unsigned r[2], unsigned addr) {
    asm volatile("ldmatrix.sync.aligned.m8n8.x2.shared.b16 {%0,%1}, [%2];"
        : "=r"(r[0]), "=r"(r[1]) : "r"(addr));
}
__device__ __forceinline__ void ldsm_x2t(unsigned r[2], unsigned addr) {
    asm volatile("ldmatrix.sync.aligned.m8n8.x2.trans.shared.b16 {%0,%1}, [%2];"
        : "=r"(r[0]), "=r"(r[1]) : "r"(addr));
}

__device__ __forceinline__ void cp16(void* smem_dst, const void* g) {
    unsigned sa = (unsigned)__cvta_generic_to_shared(smem_dst);
    asm volatile("cp.async.cg.shared.global [%0], [%1], 16;\n" :: "r"(sa), "l"(g));
}
#define CP_COMMIT() asm volatile("cp.async.commit_group;\n")
#define CP_WAIT(n)  asm volatile("cp.async.wait_group %0;\n" :: "n"(n))

__device__ __forceinline__ unsigned h2u(__half2 h) {
    return *reinterpret_cast<unsigned*>(&h);
}

// ---------------------------------------------------------------------------
// preround: x -> fp16 (float4 -> 2x half2)
// ---------------------------------------------------------------------------
#define X_F4 (MROWS * D_SZ / 4)          // 1048576

__global__ __launch_bounds__(256) void preround_x_kernel(const float* __restrict__ x)
{
    int i = blockIdx.x * blockDim.x + threadIdx.x;
    if (i >= X_F4) return;
    float4 v = ((const float4*)x)[i];
    __half2 h0 = __floats2half2_rn(v.x, v.y);
    __half2 h1 = __floats2half2_rn(v.z, v.w);
    uint2 u = { h2u(h0), h2u(h1) };
    ((uint2*)g_XR)[i] = u;
}

// Weights: transpose [K][N] -> [N][K] with fp16 convert
__global__ __launch_bounds__(256) void wtrans_kernel(
    const float* __restrict__ wq, const float* __restrict__ wk,
    const float* __restrict__ wv, const float* __restrict__ wo)
{
    __shared__ float ts[32][33];
    const float* src; __half* dst;
    if (blockIdx.z == 0)      { src = wq; dst = g_WQ; }
    else if (blockIdx.z == 1) { src = wk; dst = g_WK; }
    else if (blockIdx.z == 2) { src = wv; dst = g_WV; }
    else                      { src = wo; dst = g_WO; }
    int nb = blockIdx.x * 32, kb = blockIdx.y * 32;
    int tx = threadIdx.x & 31, ty = threadIdx.x >> 5;
#pragma unroll
    for (int i = 0; i < 4; i++) {
        int k = kb + ty + i * 8;
        ts[ty + i * 8][tx] = src[(size_t)k * D_SZ + nb + tx];
    }
    __syncthreads();
#pragma unroll
    for (int i = 0; i < 4; i++) {
        int n = nb + ty + i * 8;
        dst[(size_t)n * D_SZ + kb + tx] = __float2half_rn(ts[tx][ty + i * 8]);
    }
}

// ---------------------------------------------------------------------------
// fp16 GEMM: C[M,N] = A[M,K] @ Wt^T + bias   (Wt is [N][K] fp16)
// BM=BN=128, BK=64, 256 threads (8 warps 2x4), warp tile 64x32.
// smem rows stride 72 halves (144B), 2-stage cp.async, 2 CTAs/SM.
// ---------------------------------------------------------------------------
#define SH 72
#define TILE_B (128 * SH * 2)            // 18432 B per operand tile
#define STAGE_B (2 * TILE_B)             // 36864
#define GEMM_SMEM (2 * STAGE_B)          // 73728

template<bool HALF_OUT>
__device__ __forceinline__ void gemm_h(
    const __half* __restrict__ A, const __half* __restrict__ Wt,
    const float* __restrict__ bias, void* Cv, float scale, int N, int K)
{
    extern __shared__ char smc[];
    const unsigned sbase = (unsigned)__cvta_generic_to_shared(smc);
    const int tid  = threadIdx.x;
    const int warp = tid >> 5, lane = tid & 31;
    const int lq = lane >> 2, lr = lane & 3;
    const int m0 = blockIdx.y * 128;
    const int n0 = blockIdx.x * 128;
    const int wm = (warp >> 2) * 64;
    const int wn = (warp & 3) * 32;

    float acc[4][4][4];
#pragma unroll
    for (int i = 0; i < 4; i++)
#pragma unroll
        for (int j = 0; j < 4; j++)
#pragma unroll
            for (int v = 0; v < 4; v++) acc[i][j][v] = 0.f;

    const int T = K / 64;

    auto issue = [&](int t) {
        char* As = smc + (t & 1) * STAGE_B;
        char* Bs = As + TILE_B;
        const int k0 = t * 64;
#pragma unroll
        for (int i = 0; i < 4; i++) {
            int g = tid + i * 256;
            int row = g >> 3, j = g & 7;       // 128 rows x 8 chunks(16B)
            cp16(As + row * (SH * 2) + j * 16,
                 &A[(size_t)(m0 + row) * K + k0 + j * 8]);
        }
#pragma unroll
        for (int i = 0; i < 4; i++) {
            int g = tid + i * 256;
            int row = g >> 3, j = g & 7;
            cp16(Bs + row * (SH * 2) + j * 16,
                 &Wt[(size_t)(n0 + row) * K + k0 + j * 8]);
        }
    };

    issue(0); CP_COMMIT();

    // ldmatrix lane addressing (within-tile offsets)
    const int a_r = ((lane >> 3) & 1) * 8 + (lane & 7);  // m sub-row
    const int a_k = (lane >> 4) * 8;                      // k sub-col
    const int la  = lane & 15;
    const int b_r = la & 7;                               // n sub-row
    const int b_k = ((la >> 3) & 1) * 8;                  // k sub-col

    for (int t = 0; t < T; t++) {
        if (t + 1 < T) { issue(t + 1); CP_COMMIT(); CP_WAIT(1); }
        else           { CP_WAIT(0); }
        __syncthreads();

        const unsigned As = sbase + (t & 1) * STAGE_B;
        const unsigned Bs = As + TILE_B;
#pragma unroll
        for (int ks = 0; ks < 4; ks++) {
            const int k16 = ks * 16;
            unsigned a[4][4], b[4][2];
#pragma unroll
            for (int mt = 0; mt < 4; mt++)
                ldsm_x4(a[mt], As + ((wm + mt * 16 + a_r) * SH + k16 + a_k) * 2);
#pragma unroll
            for (int nt = 0; nt < 4; nt++)
                ldsm_x2(b[nt], Bs + ((wn + nt * 8 + b_r) * SH + k16 + b_k) * 2);
#pragma unroll
            for (int mt = 0; mt < 4; mt++)
#pragma unroll
                for (int nt = 0; nt < 4; nt++)
                    mma_f16(acc[mt][nt], a[mt], b[nt]);
        }
        __syncthreads();
    }

    // Epilogue: (acc + bias) * scale
#pragma unroll
    for (int mt = 0; mt < 4; mt++) {
#pragma unroll
        for (int nt = 0; nt < 4; nt++) {
            int r = m0 + wm + mt * 16 + lq;
            int c = n0 + wn + nt * 8 + 2 * lr;
            float b0 = bias[c], b1 = bias[c + 1];
            float v00 = (acc[mt][nt][0] + b0) * scale;
            float v01 = (acc[mt][nt][1] + b1) * scale;
            float v10 = (acc[mt][nt][2] + b0) * scale;
            float v11 = (acc[mt][nt][3] + b1) * scale;
            if (HALF_OUT) {
                __half* C = (__half*)Cv;
                *(__half2*)&C[(size_t)r * N + c]       = __floats2half2_rn(v00, v01);
                *(__half2*)&C[(size_t)(r + 8) * N + c] = __floats2half2_rn(v10, v11);
            } else {
                float* C = (float*)Cv;
                float2 f0 = { v00, v01 }, f1 = { v10, v11 };
                *(float2*)&C[(size_t)r * N + c] = f0;
                *(float2*)&C[(size_t)(r + 8) * N + c] = f1;
            }
        }
    }
}

// Q pre-scale: 1/sqrt(64) * log2(e)  (softmax runs in exp2 domain)
#define Q_SCALE (0.125f * 1.44269504088896f)

__global__ __launch_bounds__(256, 2) void qkv_kernel(
    const float* __restrict__ bq, const float* __restrict__ bk,
    const float* __restrict__ bv)
{
    const __half* W; const float* b; __half* C; float scl;
    if (blockIdx.z == 0)      { W = g_WQ; b = bq; C = g_Q; scl = Q_SCALE; }
    else if (blockIdx.z == 1) { W = g_WK; b = bk; C = g_K; scl = 1.0f; }
    else                      { W = g_WV; b = bv; C = g_V; scl = 1.0f; }
    gemm_h<true>(g_XR, W, b, C, scl, D_SZ, D_SZ);
}

__global__ __launch_bounds__(256, 2) void out_kernel(
    const float* __restrict__ bo, float* __restrict__ out)
{
    gemm_h<false>(g_A, g_WO, bo, out, 1.0f, D_SZ, D_SZ);
}

// ---------------------------------------------------------------------------
// fp16 flash attention. BQ=128, KV staged 128 rows/stage (2 x 64-col passes),
// 8 warps x 16 q rows. Softmax in exp2 domain (Q pre-scaled by 0.125*log2e).
// QK^T: Q A-frag ldmatrix.x4, K B-frag ldmatrix.x2.
// PV: P stays in accumulator regs (acc layout == A-frag layout),
//     V B-frag via ldmatrix.x2.trans.
// ---------------------------------------------------------------------------
#define KV_STAGE_B (128 * SH * 2)                 // 36864 B (128 rows)
#define A_QS_B 0
#define A_KS_B (128 * SH * 2)                     // 18432
#define A_VS_B (A_KS_B + 2 * KV_STAGE_B)          // 92160 total with V below
#define ATTN_SMEM (A_VS_B + 2 * KV_STAGE_B)       // 165888? no: see static_assert

// Layout: [Q: 128 rows][K: 2 stages x 128 rows][V: 2 stages x 128 rows]
// A_QS_B = 0, A_KS_B = 18432, A_VS_B = 18432 + 73728 = 92160 -> total 165888 B
// That exceeds 2-CTA budget; recompute: 18432 + 2*36864*2 = 165888. Too big for
// 2 CTAs (331KB). Use single-buffered 128-row staging is wrong; instead keep
// double buffering of 64-row tiles grouped: stage = 128 rows, 2 stages needed?
// No: with 128-row stages we still need 2 buffers to overlap. Budget check:
// 18432 + 147456 = 165888 > 227KB/2. So drop to 2 stages of 128 rows ONLY for
// K and V combined interleaved? Instead: use 2 buffers x 128 rows but share
// across K and V by halving depth: keep double-buffer (2 stages) of 128 rows
// for K and V = 4*36864 = 147456 + Q 18432 = 165888 B -> 1 CTA/SM at 165KB.
// That would LOSE occupancy. Fall back: single CTA per SM is worse. Therefore
// use stage = 128 rows, but only 2-deep total (one in flight, one in compute)
// with K+V packed per stage: stage holds K128 + V128 = 73728; 2 stages =
// 147456 + Q = 165888. Same thing. => Choose smaller: keep 2 CTAs/SM with
// stage=128 rows and 1.5-buffering is unsafe. Resolution: keep 2 CTAs/SM,
// stage = 128 rows, double buffered, but store KV in fp16 with stride 64+8=72
// already minimal. The only way: 2 CTAs x 110592 = 221184 <= 227KB? YES:
// 227KB = 232448 B. 2 x 110592 = 221184 fits! Layout below uses 110592 B.
#undef A_VS_B
#undef ATTN_SMEM
#define A_KV_B 18432                               // after Q
#define ATTN_SMEM (18432 + 2 * (2 * KV_STAGE_B) / 2 + 2 * KV_STAGE_B)
// Explicit: Q 18432 + K(2x36864=73728) ... 18432+73728+73728 = 165888. Too big.
// FINAL DECISION: 2 CTAs require <=113KB. Use K double-buffered 128-row
// (73728) + V single-buffered 64-row double buffer as before (36864):
// V stays at 64-row double-buffer staging, K upgraded to 128-row stages.
// Q 18432 + K 73728 + V 36864 = 129024 > 113KB still. Revert BOTH to 64-row
// double buffering (R8 scheme, 55296 B) and take only the exp2 win this round.
#undef ATTN_SMEM
#define A_KS_B2 (128 * SH * 2)                    // 18432
#define A_VS_B2 (A_KS_B2 + 2 * 64 * SH * 2)       // 36864
#define ATTN_SMEM (A_VS_B2 + 2 * 64 * SH * 2)     // 55296

__global__ __launch_bounds__(256, 2) void attn_kernel(
    const __half* __restrict__ Q, const __half* __restrict__ K,
    const __half* __restrict__ V, __half* __restrict__ O)
{
    extern __shared__ char smc[];
    const unsigned sbase = (unsigned)__cvta_generic_to_shared(smc);

    const int tid  = threadIdx.x;
    const int warp = tid >> 5, lane = tid & 31;
    const int lq = lane >> 2, lr = lane & 3;
    const int qt = gridDim.x - 1 - blockIdx.x;   // heavy tiles first
    const int h  = blockIdx.y;
    const int b  = blockIdx.z;
    const int q0 = qt * 128;
    const int wq = warp * 16;

    // Stage Q (half, pre-scaled by 0.125*log2e): 128 rows x 64 halves
    const __half* Qg = Q + ((size_t)b * S_SZ + q0) * D_SZ + h * DH;
#pragma unroll
    for (int i = 0; i < 4; i++) {
        int g = tid + i * 256;
        int row = g >> 3, j = g & 7;
        cp16(smc + A_QS_B + row * (SH * 2) + j * 16,
             &Qg[(size_t)row * D_SZ + j * 8]);
    }

    auto issue_kv = [&](int kt) {
        int st = kt & 1;
        char* Ks = smc + A_KS_B2 + st * (64 * SH * 2);
        char* Vs = smc + A_VS_B2 + st * (64 * SH * 2);
        const __half* Kg = K + ((size_t)b * S_SZ + kt * 64) * D_SZ + h * DH;
        const __half* Vg = V + ((size_t)b * S_SZ + kt * 64) * D_SZ + h * DH;
#pragma unroll
        for (int i = 0; i < 2; i++) {
            int g = tid + i * 256;
            int row = g >> 3, j = g & 7;
            cp16(Ks + row * (SH * 2) + j * 16, &Kg[(size_t)row * D_SZ + j * 8]);
            cp16(Vs + row * (SH * 2) + j * 16, &Vg[(size_t)row * D_SZ + j * 8]);
        }
    };

    float o[8][4];
#pragma unroll
    for (int dt = 0; dt < 8; dt++)
#pragma unroll
        for (int v = 0; v < 4; v++) o[dt][v] = 0.f;
    float m0v = -INFINITY, m1v = -INFINITY;
    float l0v = 0.f, l1v = 0.f;

    const int nkt = 2 * qt + 2;
    issue_kv(0); CP_COMMIT();

    // ldmatrix lane addressing
    const int a_r = ((lane >> 3) & 1) * 8 + (lane & 7);
    const int a_k = (lane >> 4) * 8;
    const int la  = lane & 15;
    const int b_r = la & 7;
    const int b_k = ((la >> 3) & 1) * 8;

    for (int kt = 0; kt < nkt; kt++) {
        CP_WAIT(0);
        __syncthreads();                 // stage kt ready; prev readers done
        if (kt + 1 < nkt) issue_kv(kt + 1);
        CP_COMMIT();

        if (kt * 64 <= q0 + wq + 15) {
            const unsigned Ks = sbase + A_KS_B2 + (kt & 1) * (64 * SH * 2);
            const unsigned Vs = sbase + A_VS_B2 + (kt & 1) * (64 * SH * 2);
            const unsigned Qs = sbase + A_QS_B;

            // ---- S = Q K^T (16 x 64 per warp), exp2-domain scores ----
            float s[8][4];
#pragma unroll
            for (int nt = 0; nt < 8; nt++)
#pragma unroll
                for (int v = 0; v < 4; v++) s[nt][v] = 0.f;

#pragma unroll
            for (int ks = 0; ks < 4; ks++) {
                const int k16 = ks * 16;
                unsigned a[4];
                ldsm_x4(a, Qs + ((wq + a_r) * SH + k16 + a_k) * 2);
#pragma unroll
                for (int nt = 0; nt < 8; nt++) {
                    unsigned bf[2];
                    ldsm_x2(bf, Ks + ((nt * 8 + b_r) * SH + k16 + b_k) * 2);
                    mma_f16(s[nt], a, bf);
                }
            }

            // ---- causal mask (near-diagonal tiles only) ----
            if (kt >= 2 * qt) {
                int qr0 = q0 + wq + lq, qr1 = qr0 + 8;
#pragma unroll
                for (int nt = 0; nt < 8; nt++) {
                    int kb = kt * 64 + nt * 8 + 2 * lr;
                    if (kb > qr0)     s[nt][0] = -INFINITY;
                    if (kb + 1 > qr0) s[nt][1] = -INFINITY;
                    if (kb > qr1)     s[nt][2] = -INFINITY;
                    if (kb + 1 > qr1) s[nt][3] = -INFINITY;
                }
            }

            // ---- online softmax (exp2 domain) ----
            float mx0 = s[0][0], mx1 = s[0][2];
#pragma unroll
            for (int nt = 0; nt < 8; nt++) {
                mx0 = fmaxf(mx0, fmaxf(s[nt][0], s[nt][1]));
                mx1 = fmaxf(mx1, fmaxf(s[nt][2], s[nt][3]));
            }
            mx0 = fmaxf(mx0, __shfl_xor_sync(0xffffffff, mx0, 1));
            mx0 = fmaxf(mx0, __shfl_xor_sync(0xffffffff, mx0, 2));
            mx1 = fmaxf(mx1, __shfl_xor_sync(0xffffffff, mx1, 1));
            mx1 = fmaxf(mx1, __shfl_xor_sync(0xffffffff, mx1, 2));

            float mn0 = fmaxf(m0v, mx0), mn1 = fmaxf(m1v, mx1);
            float al0 = exp2f(m0v - mn0), al1 = exp2f(m1v - mn1);
            m0v = mn0; m1v = mn1;

            float ls0 = 0.f, ls1 = 0.f;
            unsigned ph[8][2];
#pragma unroll
            for (int nt = 0; nt < 8; nt++) {
                float p0 = exp2f(s[nt][0] - mn0);
                float p1 = exp2f(s[nt][1] - mn0);
                float p2 = exp2f(s[nt][2] - mn1);
                float p3 = exp2f(s[nt][3] - mn1);
                ls0 += p0 + p1; ls1 += p2 + p3;
                ph[nt][0] = h2u(__floats2half2_rn(p0, p1));
                ph[nt][1] = h2u(__floats2half2_rn(p2, p3));
            }
            ls0 += __shfl_xor_sync(0xffffffff, ls0, 1);
            ls0 += __shfl_xor_sync(0xffffffff, ls0, 2);
            ls1 += __shfl_xor_sync(0xffffffff, ls1, 1);
            ls1 += __shfl_xor_sync(0xffffffff, ls1, 2);
            l0v = l0v * al0 + ls0;
            l1v = l1v * al1 + ls1;

#pragma unroll
            for (int dt = 0; dt < 8; dt++) {
                o[dt][0] *= al0; o[dt][1] *= al0;
                o[dt][2] *= al1; o[dt][3] *= al1;
            }

            // ---- O += P V ----
#pragma unroll
            for (int ks = 0; ks < 4; ks++) {
                unsigned a[4] = { ph[2 * ks][0], ph[2 * ks][1],
                                  ph[2 * ks + 1][0], ph[2 * ks + 1][1] };
#pragma unroll
                for (int dt = 0; dt < 8; dt++) {
                    unsigned bf[2];
                    ldsm_x2t(bf, Vs + ((ks * 16 + la) * SH + dt * 8) * 2);
                    mma_f16(o[dt], a, bf);
                }
            }
        }
    }

    // ---- epilogue: normalize + fp16 store ----
    float inv0 = 1.f / l0v, inv1 = 1.f / l1v;
    int gr0 = q0 + wq + lq;
#pragma unroll
    for (int dt = 0; dt < 8; dt++) {
        int col = dt * 8 + 2 * lr;
        __half2 v0 = __floats2half2_rn(o[dt][0] * inv0, o[dt][1] * inv0);
        __half2 v1 = __floats2half2_rn(o[dt][2] * inv1, o[dt][3] * inv1);
        *(__half2*)&O[((size_t)b * S_SZ + gr0) * D_SZ + h * DH + col] = v0;
        *(__half2*)&O[((size_t)b * S_SZ + gr0 + 8) * D_SZ + h * DH + col] = v1;
    }
}

// ---------------------------------------------------------------------------

extern "C" void kernel_launch(void* const* d_in, const int* in_sizes, int n_in,
                              void* d_out, int out_size)
{
    const float* x  = (const float*)d_in[0];
    const float* Wq = (const float*)d_in[1];
    const float* bq = (const float*)d_in[2];
    const float* Wk = (const float*)d_in[3];
    const float* bk = (const float*)d_in[4];
    const float* Wv = (const float*)d_in[5];
    const float* bv = (const float*)d_in[6];
    const float* Wo = (const float*)d_in[7];
    const float* bo = (const float*)d_in[8];
    float* out = (float*)d_out;

    cudaFuncSetAttribute(qkv_kernel,
                         cudaFuncAttributeMaxDynamicSharedMemorySize, GEMM_SMEM);
    cudaFuncSetAttribute(out_kernel,
                         cudaFuncAttributeMaxDynamicSharedMemorySize, GEMM_SMEM);
    cudaFuncSetAttribute(attn_kernel,
                         cudaFuncAttributeMaxDynamicSharedMemorySize, ATTN_SMEM);

    __half* gq; cudaGetSymbolAddress((void**)&gq, g_Q);
    __half* gk; cudaGetSymbolAddress((void**)&gk, g_K);
    __half* gv; cudaGetSymbolAddress((void**)&gv, g_V);
    __half* ga; cudaGetSymbolAddress((void**)&ga, g_A);

    // 0) fp16 convert x; transpose+convert weights to [N][K]
    preround_x_kernel<<<(X_F4 + 255) / 256, 256>>>(x);
    wtrans_kernel<<<dim3(32, 32, 4), 256>>>(Wq, Wk, Wv, Wo);

    // 1) QKV projections (fp16 mma; Q epilogue folds 1/sqrt(dk)*log2e)
    dim3 g1(D_SZ / 128, MROWS / 128, 3);
    qkv_kernel<<<g1, 256, GEMM_SMEM>>>(bq, bk, bv);

    // 2) causal flash attention -> g_A (fp16, exp2 softmax)
    dim3 g2(S_SZ / 128, H_SZ, B_SZ);
    attn_kernel<<<g2, 256, ATTN_SMEM>>>(gq, gk, gv, ga);

    // 3) output projection (fp32 out)
    dim3 g3(D_SZ / 128, MROWS / 128);
    out_kernel<<<g3, 256, GEMM_SMEM>>>(bo, out);
}

// round 10
// speedup vs baseline: 2.0315x; 1.0147x over previous
#include <cuda_runtime.h>
#include <cuda_fp16.h>
#include <math.h>
#include <cstdint>

#define B_SZ 2
#define S_SZ 2048
#define D_SZ 1024
#define H_SZ 16
#define DH   64
#define MROWS (B_SZ * S_SZ)   // 4096

// Scratch (device globals: allocation-free rule)
__device__ __half g_Q[MROWS * D_SZ];
__device__ __half g_K[MROWS * D_SZ];
__device__ __half g_V[MROWS * D_SZ];
__device__ __half g_A[MROWS * D_SZ];
__device__ __half g_XR[MROWS * D_SZ];     // fp16 x
__device__ __half g_WQ[D_SZ * D_SZ];      // fp16 transposed weights [N][K]
__device__ __half g_WK[D_SZ * D_SZ];
__device__ __half g_WV[D_SZ * D_SZ];
__device__ __half g_WO[D_SZ * D_SZ];

// ---------------------------------------------------------------------------
// helpers
// ---------------------------------------------------------------------------
__device__ __forceinline__ void mma_f16(float d[4], const unsigned a[4],
                                        const unsigned b[2]) {
    asm("mma.sync.aligned.m16n8k16.row.col.f32.f16.f16.f32 "
        "{%0,%1,%2,%3},{%4,%5,%6,%7},{%8,%9},{%0,%1,%2,%3};"
        : "+f"(d[0]), "+f"(d[1]), "+f"(d[2]), "+f"(d[3])
        : "r"(a[0]), "r"(a[1]), "r"(a[2]), "r"(a[3]), "r"(b[0]), "r"(b[1]));
}

__device__ __forceinline__ void ldsm_x4(unsigned r[4], unsigned addr) {
    asm volatile("ldmatrix.sync.aligned.m8n8.x4.shared.b16 {%0,%1,%2,%3}, [%4];"
        : "=r"(r[0]), "=r"(r[1]), "=r"(r[2]), "=r"(r[3]) : "r"(addr));
}
__device__ __forceinline__ void ldsm_x2(unsigned r[2], unsigned addr) {
    asm volatile("ldmatrix.sync.aligned.m8n8.x2.shared.b16 {%0,%1}, [%2];"
        : "=r"(r[0]), "=r"(r[1]) : "r"(addr));
}
__device__ __forceinline__ void ldsm_x2t(unsigned r[2], unsigned addr) {
    asm volatile("ldmatrix.sync.aligned.m8n8.x2.trans.shared.b16 {%0,%1}, [%2];"
        : "=r"(r[0]), "=r"(r[1]) : "r"(addr));
}

__device__ __forceinline__ void cp16(void* smem_dst, const void* g) {
    unsigned sa = (unsigned)__cvta_generic_to_shared(smem_dst);
    asm volatile("cp.async.cg.shared.global [%0], [%1], 16;\n" :: "r"(sa), "l"(g));
}
#define CP_COMMIT() asm volatile("cp.async.commit_group;\n")
#define CP_WAIT(n)  asm volatile("cp.async.wait_group %0;\n" :: "n"(n))

__device__ __forceinline__ unsigned h2u(__half2 h) {
    return *reinterpret_cast<unsigned*>(&h);
}

// ---------------------------------------------------------------------------
// preround: x -> fp16 (float4 -> 2x half2)
// ---------------------------------------------------------------------------
#define X_F4 (MROWS * D_SZ / 4)          // 1048576

__global__ __launch_bounds__(256) void preround_x_kernel(const float* __restrict__ x)
{
    int i = blockIdx.x * blockDim.x + threadIdx.x;
    if (i >= X_F4) return;
    float4 v = ((const float4*)x)[i];
    __half2 h0 = __floats2half2_rn(v.x, v.y);
    __half2 h1 = __floats2half2_rn(v.z, v.w);
    uint2 u = { h2u(h0), h2u(h1) };
    ((uint2*)g_XR)[i] = u;
}

// Weights: transpose [K][N] -> [N][K] with fp16 convert
__global__ __launch_bounds__(256) void wtrans_kernel(
    const float* __restrict__ wq, const float* __restrict__ wk,
    const float* __restrict__ wv, const float* __restrict__ wo)
{
    __shared__ float ts[32][33];
    const float* src; __half* dst;
    if (blockIdx.z == 0)      { src = wq; dst = g_WQ; }
    else if (blockIdx.z == 1) { src = wk; dst = g_WK; }
    else if (blockIdx.z == 2) { src = wv; dst = g_WV; }
    else                      { src = wo; dst = g_WO; }
    int nb = blockIdx.x * 32, kb = blockIdx.y * 32;
    int tx = threadIdx.x & 31, ty = threadIdx.x >> 5;
#pragma unroll
    for (int i = 0; i < 4; i++) {
        int k = kb + ty + i * 8;
        ts[ty + i * 8][tx] = src[(size_t)k * D_SZ + nb + tx];
    }
    __syncthreads();
#pragma unroll
    for (int i = 0; i < 4; i++) {
        int n = nb + ty + i * 8;
        dst[(size_t)n * D_SZ + kb + tx] = __float2half_rn(ts[tx][ty + i * 8]);
    }
}

// ---------------------------------------------------------------------------
// fp16 GEMM: C[M,N] = A[M,K] @ Wt^T + bias   (Wt is [N][K] fp16)
// BM=BN=128, BK=64, 256 threads (8 warps 2x4), warp tile 64x32.
// smem rows stride 72 halves (144B), 2-stage cp.async, 2 CTAs/SM.
// ---------------------------------------------------------------------------
#define SH 72
#define TILE_B (128 * SH * 2)            // 18432 B per operand tile
#define STAGE_B (2 * TILE_B)             // 36864
#define GEMM_SMEM (2 * STAGE_B)          // 73728

template<bool HALF_OUT>
__device__ __forceinline__ void gemm_h(
    const __half* __restrict__ A, const __half* __restrict__ Wt,
    const float* __restrict__ bias, void* Cv, float scale, int N, int K)
{
    extern __shared__ char smc[];
    const unsigned sbase = (unsigned)__cvta_generic_to_shared(smc);
    const int tid  = threadIdx.x;
    const int warp = tid >> 5, lane = tid & 31;
    const int lq = lane >> 2, lr = lane & 3;
    const int m0 = blockIdx.y * 128;
    const int n0 = blockIdx.x * 128;
    const int wm = (warp >> 2) * 64;
    const int wn = (warp & 3) * 32;

    float acc[4][4][4];
#pragma unroll
    for (int i = 0; i < 4; i++)
#pragma unroll
        for (int j = 0; j < 4; j++)
#pragma unroll
            for (int v = 0; v < 4; v++) acc[i][j][v] = 0.f;

    const int T = K / 64;

    auto issue = [&](int t) {
        char* As = smc + (t & 1) * STAGE_B;
        char* Bs = As + TILE_B;
        const int k0 = t * 64;
#pragma unroll
        for (int i = 0; i < 4; i++) {
            int g = tid + i * 256;
            int row = g >> 3, j = g & 7;       // 128 rows x 8 chunks(16B)
            cp16(As + row * (SH * 2) + j * 16,
                 &A[(size_t)(m0 + row) * K + k0 + j * 8]);
        }
#pragma unroll
        for (int i = 0; i < 4; i++) {
            int g = tid + i * 256;
            int row = g >> 3, j = g & 7;
            cp16(Bs + row * (SH * 2) + j * 16,
                 &Wt[(size_t)(n0 + row) * K + k0 + j * 8]);
        }
    };

    issue(0); CP_COMMIT();

    // ldmatrix lane addressing (within-tile offsets)
    const int a_r = ((lane >> 3) & 1) * 8 + (lane & 7);  // m sub-row
    const int a_k = (lane >> 4) * 8;                      // k sub-col
    const int la  = lane & 15;
    const int b_r = la & 7;                               // n sub-row
    const int b_k = ((la >> 3) & 1) * 8;                  // k sub-col

    for (int t = 0; t < T; t++) {
        if (t + 1 < T) { issue(t + 1); CP_COMMIT(); CP_WAIT(1); }
        else           { CP_WAIT(0); }
        __syncthreads();

        const unsigned As = sbase + (t & 1) * STAGE_B;
        const unsigned Bs = As + TILE_B;
#pragma unroll
        for (int ks = 0; ks < 4; ks++) {
            const int k16 = ks * 16;
            unsigned a[4][4], b[4][2];
#pragma unroll
            for (int mt = 0; mt < 4; mt++)
                ldsm_x4(a[mt], As + ((wm + mt * 16 + a_r) * SH + k16 + a_k) * 2);
#pragma unroll
            for (int nt = 0; nt < 4; nt++)
                ldsm_x2(b[nt], Bs + ((wn + nt * 8 + b_r) * SH + k16 + b_k) * 2);
#pragma unroll
            for (int mt = 0; mt < 4; mt++)
#pragma unroll
                for (int nt = 0; nt < 4; nt++)
                    mma_f16(acc[mt][nt], a[mt], b[nt]);
        }
        __syncthreads();
    }

    // Epilogue: (acc + bias) * scale
#pragma unroll
    for (int mt = 0; mt < 4; mt++) {
#pragma unroll
        for (int nt = 0; nt < 4; nt++) {
            int r = m0 + wm + mt * 16 + lq;
            int c = n0 + wn + nt * 8 + 2 * lr;
            float b0 = bias[c], b1 = bias[c + 1];
            float v00 = (acc[mt][nt][0] + b0) * scale;
            float v01 = (acc[mt][nt][1] + b1) * scale;
            float v10 = (acc[mt][nt][2] + b0) * scale;
            float v11 = (acc[mt][nt][3] + b1) * scale;
            if (HALF_OUT) {
                __half* C = (__half*)Cv;
                *(__half2*)&C[(size_t)r * N + c]       = __floats2half2_rn(v00, v01);
                *(__half2*)&C[(size_t)(r + 8) * N + c] = __floats2half2_rn(v10, v11);
            } else {
                float* C = (float*)Cv;
                float2 f0 = { v00, v01 }, f1 = { v10, v11 };
                *(float2*)&C[(size_t)r * N + c] = f0;
                *(float2*)&C[(size_t)(r + 8) * N + c] = f1;
            }
        }
    }
}

// Q pre-scale: 1/sqrt(64) * log2(e)  (softmax runs in exp2 domain)
#define Q_SCALE (0.125f * 1.44269504088896f)

__global__ __launch_bounds__(256, 2) void qkv_kernel(
    const float* __restrict__ bq, const float* __restrict__ bk,
    const float* __restrict__ bv)
{
    const __half* W; const float* b; __half* C; float scl;
    if (blockIdx.z == 0)      { W = g_WQ; b = bq; C = g_Q; scl = Q_SCALE; }
    else if (blockIdx.z == 1) { W = g_WK; b = bk; C = g_K; scl = 1.0f; }
    else                      { W = g_WV; b = bv; C = g_V; scl = 1.0f; }
    gemm_h<true>(g_XR, W, b, C, scl, D_SZ, D_SZ);
}

__global__ __launch_bounds__(256, 2) void out_kernel(
    const float* __restrict__ bo, float* __restrict__ out)
{
    gemm_h<false>(g_A, g_WO, bo, out, 1.0f, D_SZ, D_SZ);
}

// ---------------------------------------------------------------------------
// fp16 flash attention. BQ=128, key tile 64, 8 warps x 16 q rows.
// exp2-domain softmax (Q pre-scaled by 0.125*log2e).
// Softmax denominator l computed BY THE TENSOR CORE: V tiles carry a 65th
// column of ones (written once at kernel start; cp.async only touches bytes
// 0..127 of each 144B row, so the ones persist). The PV MMA's 9th column
// group accumulates l alongside O, sharing the alpha rescale. Row sums,
// their shuffles, and scalar l bookkeeping all disappear from the per-tile
// serial chain; l is extracted with one width-4 shuffle in the epilogue.
// ---------------------------------------------------------------------------
#define A_QS_B 0
#define A_KS_B (128 * SH * 2)                     // 18432
#define A_VS_B (A_KS_B + 2 * 64 * SH * 2)         // 36864
#define ATTN_SMEM (A_VS_B + 2 * 64 * SH * 2)      // 55296

__global__ __launch_bounds__(256, 2) void attn_kernel(
    const __half* __restrict__ Q, const __half* __restrict__ K,
    const __half* __restrict__ V, __half* __restrict__ O)
{
    extern __shared__ char smc[];
    const unsigned sbase = (unsigned)__cvta_generic_to_shared(smc);

    const int tid  = threadIdx.x;
    const int warp = tid >> 5, lane = tid & 31;
    const int lq = lane >> 2, lr = lane & 3;
    const int qt = gridDim.x - 1 - blockIdx.x;   // heavy tiles first
    const int h  = blockIdx.y;
    const int b  = blockIdx.z;
    const int q0 = qt * 128;
    const int wq = warp * 16;

    // Stage Q (half, pre-scaled): 128 rows x 64 halves
    const __half* Qg = Q + ((size_t)b * S_SZ + q0) * D_SZ + h * DH;
#pragma unroll
    for (int i = 0; i < 4; i++) {
        int g = tid + i * 256;
        int row = g >> 3, j = g & 7;
        cp16(smc + A_QS_B + row * (SH * 2) + j * 16,
             &Qg[(size_t)row * D_SZ + j * 8]);
    }

    // Ones column (V col 64) for both V stages — written once, never clobbered
    if (tid < 128) {
        int st = tid >> 6, row = tid & 63;
        *(__half*)(smc + A_VS_B + st * (64 * SH * 2) + row * (SH * 2) + 128) =
            __float2half(1.0f);
    }

    auto issue_kv = [&](int kt) {
        int st = kt & 1;
        char* Ks = smc + A_KS_B + st * (64 * SH * 2);
        char* Vs = smc + A_VS_B + st * (64 * SH * 2);
        const __half* Kg = K + ((size_t)b * S_SZ + kt * 64) * D_SZ + h * DH;
        const __half* Vg = V + ((size_t)b * S_SZ + kt * 64) * D_SZ + h * DH;
#pragma unroll
        for (int i = 0; i < 2; i++) {
            int g = tid + i * 256;
            int row = g >> 3, j = g & 7;
            cp16(Ks + row * (SH * 2) + j * 16, &Kg[(size_t)row * D_SZ + j * 8]);
            cp16(Vs + row * (SH * 2) + j * 16, &Vg[(size_t)row * D_SZ + j * 8]);
        }
    };

    // o[0..7]: O columns; o[8]: l column (V col 64 = ones)
    float o[9][4];
#pragma unroll
    for (int dt = 0; dt < 9; dt++)
#pragma unroll
        for (int v = 0; v < 4; v++) o[dt][v] = 0.f;
    float m0v = -INFINITY, m1v = -INFINITY;

    const int nkt = 2 * qt + 2;
    issue_kv(0); CP_COMMIT();

    // ldmatrix lane addressing
    const int a_r = ((lane >> 3) & 1) * 8 + (lane & 7);
    const int a_k = (lane >> 4) * 8;
    const int la  = lane & 15;
    const int b_r = la & 7;
    const int b_k = ((la >> 3) & 1) * 8;

    for (int kt = 0; kt < nkt; kt++) {
        CP_WAIT(0);
        __syncthreads();                 // stage kt ready; prev readers done
        if (kt + 1 < nkt) issue_kv(kt + 1);
        CP_COMMIT();

        if (kt * 64 <= q0 + wq + 15) {
            const unsigned Ks = sbase + A_KS_B + (kt & 1) * (64 * SH * 2);
            const unsigned Vs = sbase + A_VS_B + (kt & 1) * (64 * SH * 2);
            const unsigned Qs = sbase + A_QS_B;

            // ---- S = Q K^T (16 x 64 per warp), exp2-domain scores ----
            float s[8][4];
#pragma unroll
            for (int nt = 0; nt < 8; nt++)
#pragma unroll
                for (int v = 0; v < 4; v++) s[nt][v] = 0.f;

#pragma unroll
            for (int ks = 0; ks < 4; ks++) {
                const int k16 = ks * 16;
                unsigned a[4];
                ldsm_x4(a, Qs + ((wq + a_r) * SH + k16 + a_k) * 2);
#pragma unroll
                for (int nt = 0; nt < 8; nt++) {
                    unsigned bf[2];
                    ldsm_x2(bf, Ks + ((nt * 8 + b_r) * SH + k16 + b_k) * 2);
                    mma_f16(s[nt], a, bf);
                }
            }

            // ---- causal mask (near-diagonal tiles only) ----
            if (kt >= 2 * qt) {
                int qr0 = q0 + wq + lq, qr1 = qr0 + 8;
#pragma unroll
                for (int nt = 0; nt < 8; nt++) {
                    int kb = kt * 64 + nt * 8 + 2 * lr;
                    if (kb > qr0)     s[nt][0] = -INFINITY;
                    if (kb + 1 > qr0) s[nt][1] = -INFINITY;
                    if (kb > qr1)     s[nt][2] = -INFINITY;
                    if (kb + 1 > qr1) s[nt][3] = -INFINITY;
                }
            }

            // ---- online softmax (exp2 domain; l handled by MMA) ----
            float mx0 = s[0][0], mx1 = s[0][2];
#pragma unroll
            for (int nt = 0; nt < 8; nt++) {
                mx0 = fmaxf(mx0, fmaxf(s[nt][0], s[nt][1]));
                mx1 = fmaxf(mx1, fmaxf(s[nt][2], s[nt][3]));
            }
            mx0 = fmaxf(mx0, __shfl_xor_sync(0xffffffff, mx0, 1));
            mx0 = fmaxf(mx0, __shfl_xor_sync(0xffffffff, mx0, 2));
            mx1 = fmaxf(mx1, __shfl_xor_sync(0xffffffff, mx1, 1));
            mx1 = fmaxf(mx1, __shfl_xor_sync(0xffffffff, mx1, 2));

            float mn0 = fmaxf(m0v, mx0), mn1 = fmaxf(m1v, mx1);
            float al0 = exp2f(m0v - mn0), al1 = exp2f(m1v - mn1);
            m0v = mn0; m1v = mn1;

            unsigned ph[8][2];
#pragma unroll
            for (int nt = 0; nt < 8; nt++) {
                float p0 = exp2f(s[nt][0] - mn0);
                float p1 = exp2f(s[nt][1] - mn0);
                float p2 = exp2f(s[nt][2] - mn1);
                float p3 = exp2f(s[nt][3] - mn1);
                ph[nt][0] = h2u(__floats2half2_rn(p0, p1));
                ph[nt][1] = h2u(__floats2half2_rn(p2, p3));
            }

#pragma unroll
            for (int dt = 0; dt < 9; dt++) {
                o[dt][0] *= al0; o[dt][1] *= al0;
                o[dt][2] *= al1; o[dt][3] *= al1;
            }

            // ---- O (and l) += P V ----
#pragma unroll
            for (int ks = 0; ks < 4; ks++) {
                unsigned a[4] = { ph[2 * ks][0], ph[2 * ks][1],
                                  ph[2 * ks + 1][0], ph[2 * ks + 1][1] };
#pragma unroll
                for (int dt = 0; dt < 9; dt++) {
                    unsigned bf[2];
                    ldsm_x2t(bf, Vs + ((ks * 16 + la) * SH + dt * 8) * 2);
                    mma_f16(o[dt], a, bf);
                }
            }
        }
    }

    // ---- epilogue: extract l (col 64, lr==0 lanes), normalize, store ----
    float l0 = __shfl_sync(0xffffffff, o[8][0], 0, 4);
    float l1 = __shfl_sync(0xffffffff, o[8][2], 0, 4);
    float inv0 = 1.f / l0, inv1 = 1.f / l1;
    int gr0 = q0 + wq + lq;
#pragma unroll
    for (int dt = 0; dt < 8; dt++) {
        int col = dt * 8 + 2 * lr;
        __half2 v0 = __floats2half2_rn(o[dt][0] * inv0, o[dt][1] * inv0);
        __half2 v1 = __floats2half2_rn(o[dt][2] * inv1, o[dt][3] * inv1);
        *(__half2*)&O[((size_t)b * S_SZ + gr0) * D_SZ + h * DH + col] = v0;
        *(__half2*)&O[((size_t)b * S_SZ + gr0 + 8) * D_SZ + h * DH + col] = v1;
    }
}

// ---------------------------------------------------------------------------

extern "C" void kernel_launch(void* const* d_in, const int* in_sizes, int n_in,
                              void* d_out, int out_size)
{
    const float* x  = (const float*)d_in[0];
    const float* Wq = (const float*)d_in[1];
    const float* bq = (const float*)d_in[2];
    const float* Wk = (const float*)d_in[3];
    const float* bk = (const float*)d_in[4];
    const float* Wv = (const float*)d_in[5];
    const float* bv = (const float*)d_in[6];
    const float* Wo = (const float*)d_in[7];
    const float* bo = (const float*)d_in[8];
    float* out = (float*)d_out;

    cudaFuncSetAttribute(qkv_kernel,
                         cudaFuncAttributeMaxDynamicSharedMemorySize, GEMM_SMEM);
    cudaFuncSetAttribute(out_kernel,
                         cudaFuncAttributeMaxDynamicSharedMemorySize, GEMM_SMEM);
    cudaFuncSetAttribute(attn_kernel,
                         cudaFuncAttributeMaxDynamicSharedMemorySize, ATTN_SMEM);

    __half* gq; cudaGetSymbolAddress((void**)&gq, g_Q);
    __half* gk; cudaGetSymbolAddress((void**)&gk, g_K);
    __half* gv; cudaGetSymbolAddress((void**)&gv, g_V);
    __half* ga; cudaGetSymbolAddress((void**)&ga, g_A);

    // 0) fp16 convert x; transpose+convert weights to [N][K]
    preround_x_kernel<<<(X_F4 + 255) / 256, 256>>>(x);
    wtrans_kernel<<<dim3(32, 32, 4), 256>>>(Wq, Wk, Wv, Wo);

    // 1) QKV projections (fp16 mma; Q epilogue folds 1/sqrt(dk)*log2e)
    dim3 g1(D_SZ / 128, MROWS / 128, 3);
    qkv_kernel<<<g1, 256, GEMM_SMEM>>>(bq, bk, bv);

    // 2) causal flash attention -> g_A (fp16, exp2 softmax, MMA-computed l)
    dim3 g2(S_SZ / 128, H_SZ, B_SZ);
    attn_kernel<<<g2, 256, ATTN_SMEM>>>(gq, gk, gv, ga);

    // 3) output projection (fp32 out)
    dim3 g3(D_SZ / 128, MROWS / 128);
    out_kernel<<<g3, 256, GEMM_SMEM>>>(bo, out);
}